// round 15
// baseline (speedup 1.0000x reference)
#include <cuda_runtime.h>
#include <cstdint>

#define HEADS 8
#define BATCH 8
#define SEQ   1024
#define HID   512
#define DK    64
#define NH    (HEADS*BATCH)
#define TOPK  51
#define SCALE 1.2f

#define SSTRIDE 1025   /* row-major score stride (odd: conflict-free) */
#define TSTRIDE 34     /* transposed stride: even (8B pairs), 2-way banks */

__device__ float g_Qt[(size_t)NH * DK * SEQ];
__device__ float g_Kt[(size_t)NH * DK * SEQ];
__device__ float g_V [(size_t)NH * SEQ * DK];
__device__ float g_attn[(size_t)BATCH * SEQ * HID];

__device__ __forceinline__ void cp16(float* dst, const float* src) {
    unsigned u = (unsigned)__cvta_generic_to_shared(dst);
    asm volatile("cp.async.cg.shared.global [%0], [%1], 16;\n" :: "r"(u), "l"(src));
}
__device__ __forceinline__ void cp_commit() { asm volatile("cp.async.commit_group;\n" ::: "memory"); }
__device__ __forceinline__ void cp_wait1()  { asm volatile("cp.async.wait_group 1;\n" ::: "memory"); }
__device__ __forceinline__ void cp_wait0()  { asm volatile("cp.async.wait_group 0;\n" ::: "memory"); }
__device__ __forceinline__ float ex2f(float x) {
    float r; asm("ex2.approx.ftz.f32 %0, %1;" : "=f"(r) : "f"(x)); return r;
}
__device__ __forceinline__ uint64_t dup2(float x) {
    uint64_t r; asm("mov.b64 %0, {%1, %1};" : "=l"(r) : "f"(x)); return r;
}
__device__ __forceinline__ void fma2(uint64_t& d, uint64_t a, uint64_t b) {
    asm("fma.rn.f32x2 %0, %1, %2, %0;" : "+l"(d) : "l"(a), "l"(b));
}
__device__ __forceinline__ float2 unpack2(uint64_t v) {
    float2 r; asm("mov.b64 {%0, %1}, %2;" : "=f"(r.x), "=f"(r.y) : "l"(v)); return r;
}

// ================= SGEMM (unchanged R13 FFMA2 version) =================
__global__ void __launch_bounds__(256) sgemm512(
    const float* __restrict__ X, const float* __restrict__ W,
    const float* __restrict__ bias, float* __restrict__ out, int mode)
{
    __shared__ float As[16][68];
    __shared__ float Bs[16][64];
    const int tid = threadIdx.x;
    const int tx = tid & 15, ty = tid >> 4;
    const int bm = blockIdx.y * 64, bn = blockIdx.x * 64;
    const int am = tid >> 2, ak = (tid & 3) << 2;
    const int wk = tid >> 4, wn = (tid & 15) << 2;
    uint64_t acc[4][2] = {};
    for (int k0 = 0; k0 < 512; k0 += 16) {
        float4 xa = *(const float4*)&X[(bm + am) * 512 + k0 + ak];
        float4 wb = *(const float4*)&W[(k0 + wk) * 512 + bn + wn];
        __syncthreads();
        As[ak + 0][am] = xa.x; As[ak + 1][am] = xa.y;
        As[ak + 2][am] = xa.z; As[ak + 3][am] = xa.w;
        *(float4*)&Bs[wk][wn] = wb;
        __syncthreads();
#pragma unroll
        for (int kk = 0; kk < 16; kk++) {
            const float4 a4 = *(const float4*)&As[kk][ty * 4];
            const ulonglong2 b2 = *(const ulonglong2*)&Bs[kk][tx * 4];
            const uint64_t d0 = dup2(a4.x), d1 = dup2(a4.y), d2 = dup2(a4.z), d3 = dup2(a4.w);
            fma2(acc[0][0], d0, b2.x); fma2(acc[0][1], d0, b2.y);
            fma2(acc[1][0], d1, b2.x); fma2(acc[1][1], d1, b2.y);
            fma2(acc[2][0], d2, b2.x); fma2(acc[2][1], d2, b2.y);
            fma2(acc[3][0], d3, b2.x); fma2(acc[3][1], d3, b2.y);
        }
    }
    float accf[4][4];
#pragma unroll
    for (int i = 0; i < 4; i++) {
        const float2 p0 = unpack2(acc[i][0]);
        const float2 p1 = unpack2(acc[i][1]);
        accf[i][0] = p0.x; accf[i][1] = p0.y; accf[i][2] = p1.x; accf[i][3] = p1.y;
    }
    const float4 bb4 = *(const float4*)(bias + bn + tx * 4);
    const float bb[4] = {bb4.x, bb4.y, bb4.z, bb4.w};
    const int m0 = bm + ty * 4;
    const int n0 = bn + tx * 4;
    if (mode == 2) {
#pragma unroll
        for (int i = 0; i < 4; i++) {
            float4 o = make_float4(accf[i][0] + bb[0], accf[i][1] + bb[1],
                                   accf[i][2] + bb[2], accf[i][3] + bb[3]);
            *(float4*)(out + (m0 + i) * 512 + n0) = o;
        }
    } else if (mode == 1) {
        const int h = n0 >> 6, c = n0 & 63;
        const int b_ = m0 >> 10, s = m0 & 1023;
        float* base = out + ((h * 8 + b_) * SEQ + s) * DK + c;
#pragma unroll
        for (int i = 0; i < 4; i++) {
            float4 o = make_float4(accf[i][0] + bb[0], accf[i][1] + bb[1],
                                   accf[i][2] + bb[2], accf[i][3] + bb[3]);
            *(float4*)(base + i * DK) = o;
        }
    } else {
        const int h = n0 >> 6;
        const int b_ = m0 >> 10, s = m0 & 1023;
        float* base = out + (h * 8 + b_) * DK * SEQ + s;
#pragma unroll
        for (int j = 0; j < 4; j++) {
            const int c = (n0 & 63) + j;
            float4 o = make_float4(accf[0][j] + bb[j], accf[1][j] + bb[j],
                                   accf[2][j] + bb[j], accf[3][j] + bb[j]);
            *(float4*)(base + c * SEQ) = o;
        }
    }
}

// ================= attention =================
#define KVBUF 8704
#define SQ_FLOATS 2048
#define SS_FLOATS (SEQ * TSTRIDE)                       /* 34816 >= 32*SSTRIDE */
#define ATTN_SMEM_BYTES ((SQ_FLOATS + SS_FLOATS + 2*KVBUF) * 4)  /* 217088 */

__device__ __forceinline__ void load_k_chunk(float* buf, const float* gK, int kc, int tid) {
#pragma unroll
    for (int j = 0; j < 4; j++) {
        int f = tid + 512 * j;
        int c = f >> 5;
        int kk = (f & 31) << 2;
        cp16(buf + c * 128 + kk, gK + c * SEQ + kc * 128 + kk);
    }
}
__device__ __forceinline__ void load_v_chunk(float* buf, const float* gV, int kc, int tid) {
#pragma unroll
    for (int j = 0; j < 4; j++) {
        int f = tid + 512 * j;
        int key = f >> 4;
        int c4 = (f & 15) << 2;
        cp16(buf + key * 68 + c4, gV + (kc * 128 + key) * DK + c4);
    }
}

__global__ void __launch_bounds__(512, 1) attn_kernel(const int* __restrict__ randidx, int n_rand)
{
    extern __shared__ float sm[];
    float* sQt  = sm;                        // [64][32]
    float* sS   = sm + SQ_FLOATS;            // row-major then transposed (reuse)
    float* sKV0 = sm + SQ_FLOATS + SS_FLOATS;
    float* sKV1 = sKV0 + KVBUF;
    __shared__ unsigned sRand[32];

    const int tid  = threadIdx.x;
    const int lane = tid & 31;
    const int warp = tid >> 5;
    const int qb = blockIdx.x;
    const int n  = blockIdx.y;

    const float* gQ = g_Qt + n * (DK * SEQ);
    const float* gK = g_Kt + n * (DK * SEQ);
    const float* gV = g_V  + n * (SEQ * DK);

    load_k_chunk(sKV0, gK, 0, tid);
    cp_commit();

    if (tid < 32) sRand[tid] = 0u;
    {
        int c = tid >> 3, s4 = (tid & 7) << 2;
        float4 v = *(const float4*)(gQ + c * SEQ + qb * 32 + s4);
        v.x *= 0.125f; v.y *= 0.125f; v.z *= 0.125f; v.w *= 0.125f;
        *(float4*)(sQt + c * 32 + s4) = v;
    }
    __syncthreads();
    if (tid < n_rand) {
        int v = randidx[tid] & (SEQ - 1);
        atomicOr(&sRand[v >> 5], 1u << (v & 31));
    }

    // ---- scores: thread = 8 rows x 1 key; Q pairs natural, warp-broadcast ----
    {
        const int key  = tid & 127;          // warp: 32 consecutive keys
        const int rowg = tid >> 7;           // warp-uniform
        const int r0   = rowg * 8;
        const float* qp = sQt + r0;
        for (int kc = 0; kc < 8; kc++) {
            if (kc < 7) {
                load_k_chunk((kc & 1) ? sKV0 : sKV1, gK, kc + 1, tid);
                cp_commit();
                cp_wait1();
            } else {
                cp_wait0();
            }
            __syncthreads();
            const float* kp = ((kc & 1) ? sKV1 : sKV0) + key;
            uint64_t a01 = 0, a23 = 0, a45 = 0, a67 = 0;
#pragma unroll 16
            for (int c = 0; c < 64; c++) {
                const ulonglong2 qA = *(const ulonglong2*)(qp + c * 32);     // rows r0..r0+3 (bcast)
                const ulonglong2 qB = *(const ulonglong2*)(qp + c * 32 + 4); // rows r0+4..r0+7
                const uint64_t kd = dup2(kp[c * 128]);
                fma2(a01, qA.x, kd); fma2(a23, qA.y, kd);
                fma2(a45, qB.x, kd); fma2(a67, qB.y, kd);
            }
            float* sp = sS + r0 * SSTRIDE + kc * 128 + key;
            float2 p;
            p = unpack2(a01); sp[0] = p.x;           sp[SSTRIDE] = p.y;
            p = unpack2(a23); sp[2 * SSTRIDE] = p.x; sp[3 * SSTRIDE] = p.y;
            p = unpack2(a45); sp[4 * SSTRIDE] = p.x; sp[5 * SSTRIDE] = p.y;
            p = unpack2(a67); sp[6 * SSTRIDE] = p.x; sp[7 * SSTRIDE] = p.y;
            __syncthreads();
        }
    }

    load_v_chunk(sKV0, gV, 0, tid);
    cp_commit();

    // ---- topk: read both rows -> barrier -> process & write TRANSPOSED ----
    {
        float e[2][32];
        const int rbase = warp * 2;
#pragma unroll
        for (int rr = 0; rr < 2; rr++) {
            const float* row = sS + (rbase + rr) * SSTRIDE;
#pragma unroll
            for (int i = 0; i < 32; i++) e[rr][i] = row[lane + 32 * i];
        }
        __syncthreads();                     // all raw reads done before transpose writes
#pragma unroll 1
        for (int rr = 0; rr < 2; rr++) {
            const int r = rbase + rr;
            float m = -3.0e38f;
#pragma unroll
            for (int i = 0; i < 32; i++) m = fmaxf(m, e[rr][i]);
#pragma unroll
            for (int off = 16; off; off >>= 1) m = fmaxf(m, __shfl_xor_sync(0xFFFFFFFFu, m, off));
#pragma unroll
            for (int i = 0; i < 32; i++) e[rr][i] = ex2f((e[rr][i] - m) * 1.4426950408889634f);

            unsigned prefix = 0u;
#pragma unroll 1
            for (int bit = 29; bit >= 0; bit--) {
                const unsigned cand = prefix | (1u << bit);
                int c = 0;
#pragma unroll
                for (int i = 0; i < 32; i++) c += (__float_as_uint(e[rr][i]) >= cand) ? 1 : 0;
                c = __reduce_add_sync(0xFFFFFFFFu, c);
                if (c >= TOPK) {
                    prefix = cand;
                    if (c == TOPK) break;
                }
            }
            float s = 0.0f;
#pragma unroll
            for (int i = 0; i < 32; i++) {
                bool sel = (__float_as_uint(e[rr][i]) >= prefix) || ((sRand[i] >> lane) & 1u);
                e[rr][i] = sel ? e[rr][i] * SCALE : e[rr][i];
                s += e[rr][i];
            }
#pragma unroll
            for (int off = 16; off; off >>= 1) s += __shfl_xor_sync(0xFFFFFFFFu, s, off);
            const float inv = 1.0f / s;
#pragma unroll
            for (int i = 0; i < 32; i++) sS[(lane + 32 * i) * TSTRIDE + r] = e[rr][i] * inv;
        }
    }
    __syncthreads();                         // transpose complete before AV reads

    // ---- AV: thread = 8 rows x 2 cols, 4-way k-split; S pairs broadcast ----
    {
        const int rowg = warp & 3;           // warp-uniform
        const int kq   = warp >> 2;          // warp-uniform
        const int r0 = rowg * 8;
        const int c0 = lane * 2;
        const int kb = kq * 32;
        uint64_t acc[4][2] = {};             // [rowpair][col]
        for (int kc = 0; kc < 8; kc++) {
            if (kc < 7) {
                load_v_chunk((kc & 1) ? sKV0 : sKV1, gV, kc + 1, tid);
                cp_commit();
                cp_wait1();
            } else {
                cp_wait0();
            }
            __syncthreads();
            const float* Vb = ((kc & 1) ? sKV1 : sKV0) + c0;
            const float* St = sS + (kc * 128 + kb) * TSTRIDE + r0;
#pragma unroll 4
            for (int kk = 0; kk < 32; kk++) {
                const float* st = St + kk * TSTRIDE;
                const uint64_t s01 = *(const uint64_t*)(st);      // bcast
                const uint64_t s23 = *(const uint64_t*)(st + 2);
                const uint64_t s45 = *(const uint64_t*)(st + 4);
                const uint64_t s67 = *(const uint64_t*)(st + 6);
                const float2 v = *(const float2*)(Vb + (kb + kk) * 68);
                const uint64_t v0 = dup2(v.x), v1 = dup2(v.y);
                fma2(acc[0][0], s01, v0); fma2(acc[0][1], s01, v1);
                fma2(acc[1][0], s23, v0); fma2(acc[1][1], s23, v1);
                fma2(acc[2][0], s45, v0); fma2(acc[2][1], s45, v1);
                fma2(acc[3][0], s67, v0); fma2(acc[3][1], s67, v1);
            }
            __syncthreads();
        }

        // reduce 4 kq-partials via sKV0 scratch
        uint64_t* scr = (uint64_t*)sKV0;
        const int g = rowg * 32 + lane;      // 0..127
        if (kq != 0) {
            uint64_t* dst = scr + ((kq - 1) * 128 + g) * 8;
#pragma unroll
            for (int j = 0; j < 4; j++) { dst[j * 2] = acc[j][0]; dst[j * 2 + 1] = acc[j][1]; }
        }
        __syncthreads();
        if (kq == 0) {
            float o[4][2][2];
#pragma unroll
            for (int j = 0; j < 4; j++) {
                float2 p0 = unpack2(acc[j][0]);
                float2 p1 = unpack2(acc[j][1]);
                o[j][0][0] = p0.x; o[j][0][1] = p1.x;   // row r0+2j
                o[j][1][0] = p0.y; o[j][1][1] = p1.y;   // row r0+2j+1
            }
#pragma unroll
            for (int p = 0; p < 3; p++) {
                const uint64_t* src = scr + (p * 128 + g) * 8;
#pragma unroll
                for (int j = 0; j < 4; j++) {
                    float2 p0 = unpack2(src[j * 2]);
                    float2 p1 = unpack2(src[j * 2 + 1]);
                    o[j][0][0] += p0.x; o[j][0][1] += p1.x;
                    o[j][1][0] += p0.y; o[j][1][1] += p1.y;
                }
            }
            const int h = n >> 3, b_ = n & 7;
            float* ob = g_attn + (b_ * SEQ + qb * 32 + r0) * HID + h * 64 + c0;
#pragma unroll
            for (int j = 0; j < 4; j++) {
                *(float2*)(ob + (2 * j) * HID)     = make_float2(o[j][0][0], o[j][0][1]);
                *(float2*)(ob + (2 * j + 1) * HID) = make_float2(o[j][1][0], o[j][1][1]);
            }
        }
    }
}

// =================================================================
extern "C" void kernel_launch(void* const* d_in, const int* in_sizes, int n_in,
                              void* d_out, int out_size) {
    const float* Qx  = (const float*)d_in[0];
    const float* KVx = (const float*)d_in[1];
    const float* Wq  = (const float*)d_in[2];
    const float* bq  = (const float*)d_in[3];
    const float* Wk  = (const float*)d_in[4];
    const float* bk  = (const float*)d_in[5];
    const float* Wv  = (const float*)d_in[6];
    const float* bv  = (const float*)d_in[7];
    const float* Wo  = (const float*)d_in[8];
    const float* bo  = (const float*)d_in[9];
    const int* ridx  = (const int*)d_in[10];
    const int n_rand = in_sizes[10];
    float* out = (float*)d_out;

    float *pQt, *pKt, *pV, *pA;
    cudaGetSymbolAddress((void**)&pQt, g_Qt);
    cudaGetSymbolAddress((void**)&pKt, g_Kt);
    cudaGetSymbolAddress((void**)&pV,  g_V);
    cudaGetSymbolAddress((void**)&pA,  g_attn);

    cudaFuncSetAttribute(attn_kernel, cudaFuncAttributeMaxDynamicSharedMemorySize, ATTN_SMEM_BYTES);

    dim3 gg(8, 128);
    sgemm512<<<gg, 256>>>(Qx,  Wq, bq, pQt, 0);
    sgemm512<<<gg, 256>>>(KVx, Wk, bk, pKt, 0);
    sgemm512<<<gg, 256>>>(KVx, Wv, bv, pV,  1);
    attn_kernel<<<dim3(32, 64), 512, ATTN_SMEM_BYTES>>>(ridx, n_rand);
    sgemm512<<<gg, 256>>>(pA, Wo, bo, out, 2);
}